// round 4
// baseline (speedup 1.0000x reference)
#include <cuda_runtime.h>

typedef unsigned long long u64;

#define Bb 64
#define Tt 512
#define Dd 1024
#define Hh 1024
#define Gblk 128   // persistent grid size (<= 148 SMs, 1 CTA/SM => co-resident)

// Scratch (allocation-free rule: __device__ globals)
__device__ float g_Gx[(size_t)Tt * Bb * 2 * Hh];  // [t][b][2H] = x@W[:D] + W_b
__device__ float g_Cx[(size_t)Tt * Bb * Hh];      // [t][b][H]  = x@U[:D] + U_b
__device__ float g_h [Bb * Hh];                   // current hidden state [b][H]
__device__ float g_rh[Bb * Hh];                   // r * h
__device__ float g_u [Bb * Hh];                   // update gate
__device__ unsigned g_arrive;                      // monotonic barrier counter

// ---- packed f32x2 helpers (sm_103a: doubles FFMA throughput vs scalar) ----
__device__ __forceinline__ u64 dup2(float x) {
    u64 r; asm("mov.b64 %0, {%1, %1};" : "=l"(r) : "f"(x)); return r;
}
__device__ __forceinline__ void fma2(u64 &d, u64 a, u64 b) {
    asm("fma.rn.f32x2 %0, %1, %2, %0;" : "+l"(d) : "l"(a), "l"(b));
}
__device__ __forceinline__ float2 unpack2(u64 v) {
    float2 f; asm("mov.b64 {%0, %1}, %2;" : "=f"(f.x), "=f"(f.y) : "l"(v)); return f;
}
__device__ __forceinline__ unsigned ld_acq(const unsigned* p) {
    unsigned v; asm volatile("ld.global.acquire.gpu.u32 %0, [%1];" : "=r"(v) : "l"(p)); return v;
}

// ============================================================================
// Precompute GEMM: out[(t*64+b), n] = sum_k x[b,t,k] * Wm[k,n] + bias[n]
// Block tile 64(rows=batch) x 64(cols), BK=32, 256 threads, 4x4 per thread.
// ============================================================================
__global__ void __launch_bounds__(256) gemm_pre(
    const float* __restrict__ X,    // x as [B*T, D], row = b*T + t
    const float* __restrict__ Wm,   // [D+H, N] row-major (only rows 0..D-1 used)
    const float* __restrict__ bias, // [N]
    int N, int which)               // which: 0 -> g_Gx, 1 -> g_Cx
{
    float* __restrict__ out = which ? g_Cx : g_Gx;
    const int t   = blockIdx.y;
    const int n0  = blockIdx.x * 64;
    const int tid = threadIdx.x;
    const int tn  = tid & 15;   // col group (cols tn*4 .. +3)
    const int tm  = tid >> 4;   // row group (rows tm*4 .. +3)

    __shared__ float As[32][64];  // [k][b]
    __shared__ float Bs[32][64];  // [k][n]

    u64 acc[2][4];
#pragma unroll
    for (int i = 0; i < 2; i++)
#pragma unroll
        for (int j = 0; j < 4; j++) acc[i][j] = 0ull;

    float4 pa[2], pb[2];

#pragma unroll
    for (int i = 0; i < 2; i++) {
        int idx = tid + i * 256;
        int m = idx & 63, kq = (idx >> 6) * 4;
        pa[i] = *reinterpret_cast<const float4*>(&X[(size_t)(m * Tt + t) * Dd + kq]);
        int n4 = (idx & 15) * 4, kk = idx >> 4;
        pb[i] = *reinterpret_cast<const float4*>(&Wm[(size_t)kk * N + n0 + n4]);
    }

    for (int kt = 0; kt < Dd / 32; ++kt) {
#pragma unroll
        for (int i = 0; i < 2; i++) {
            int idx = tid + i * 256;
            int m = idx & 63, kq = (idx >> 6) * 4;
            As[kq + 0][m] = pa[i].x; As[kq + 1][m] = pa[i].y;
            As[kq + 2][m] = pa[i].z; As[kq + 3][m] = pa[i].w;
            int n4 = (idx & 15) * 4, kk = idx >> 4;
            *reinterpret_cast<float4*>(&Bs[kk][n4]) = pb[i];
        }
        __syncthreads();
        if (kt + 1 < Dd / 32) {
            int k0 = (kt + 1) * 32;
#pragma unroll
            for (int i = 0; i < 2; i++) {
                int idx = tid + i * 256;
                int m = idx & 63, kq = (idx >> 6) * 4;
                pa[i] = *reinterpret_cast<const float4*>(&X[(size_t)(m * Tt + t) * Dd + k0 + kq]);
                int n4 = (idx & 15) * 4, kk = idx >> 4;
                pb[i] = *reinterpret_cast<const float4*>(&Wm[(size_t)(k0 + kk) * N + n0 + n4]);
            }
        }
#pragma unroll
        for (int k = 0; k < 32; k++) {
            longlong2 a = *reinterpret_cast<const longlong2*>(&As[k][tm * 4]);
            float4 b4 = *reinterpret_cast<const float4*>(&Bs[k][tn * 4]);
            u64 b0 = dup2(b4.x), b1 = dup2(b4.y), b2 = dup2(b4.z), b3 = dup2(b4.w);
            fma2(acc[0][0], (u64)a.x, b0); fma2(acc[1][0], (u64)a.y, b0);
            fma2(acc[0][1], (u64)a.x, b1); fma2(acc[1][1], (u64)a.y, b1);
            fma2(acc[0][2], (u64)a.x, b2); fma2(acc[1][2], (u64)a.y, b2);
            fma2(acc[0][3], (u64)a.x, b3); fma2(acc[1][3], (u64)a.y, b3);
        }
        __syncthreads();
    }

#pragma unroll
    for (int j = 0; j < 4; j++) {
        int n = n0 + tn * 4 + j;
        float bv = bias[n];
#pragma unroll
        for (int i = 0; i < 2; i++) {
            float2 v = unpack2(acc[i][j]);
            int b0r = tm * 4 + i * 2;
            out[(size_t)(t * Bb + b0r    ) * N + n] = v.x + bv;
            out[(size_t)(t * Bb + b0r + 1) * N + n] = v.y + bv;
        }
    }
}

__global__ void copy_h0(const float* __restrict__ h0)
{
    int i = blockIdx.x * blockDim.x + threadIdx.x;
    if (i < Bb * Hh) g_h[i] = h0[i];
}

// ============================================================================
// Persistent recurrence kernel: 512 steps, 2 grid barriers per step.
// Phase A (gate): per block 16 cols of 2048:
//   pre = h @ W[D:,:] + Gx[t]; sigmoid; n<H -> rh=r*h, n>=H -> u
// Phase B (cand): per block 8 cols of 1024:
//   c = tanh(rh @ U[D:,:] + Cx[t]); h = u*h + (1-u)*c; out[b][t][n] = h
// Grid barrier: monotonic arrive counter, targets relative to entry base
// (no reset -> no reset race; replay-safe; unsigned-wrap-safe).
// ============================================================================
__global__ void __launch_bounds__(256) gru_persist(
    const float* __restrict__ W, const float* __restrict__ U,
    float* __restrict__ out)
{
    const int tid = threadIdx.x;
    __shared__ float  hs[64][64];
    __shared__ float2 ws[64][16];
    __shared__ unsigned s_base;

    if (tid == 0) s_base = ld_acq(&g_arrive);
    __syncthreads();
    const unsigned base = s_base;
    unsigned epoch = 0;

#define GRID_BAR()                                                         \
    do {                                                                   \
        __syncthreads();                                                   \
        epoch++;                                                           \
        if (tid == 0) {                                                    \
            __threadfence();                                               \
            atomicAdd(&g_arrive, 1u);                                      \
            while ((unsigned)(ld_acq(&g_arrive) - base) < epoch * Gblk) ;  \
        }                                                                  \
        __syncthreads();                                                   \
    } while (0)

    const float* __restrict__ Wg = W + (size_t)Dd * (2 * Hh) + blockIdx.x * 16;
    const float* __restrict__ Ug = U + (size_t)Dd * Hh + blockIdx.x * 8;

    for (int t = 0; t < Tt; ++t) {
        // ---------------- Phase A: gates ----------------
        {
            const int n0  = blockIdx.x * 16;
            const int col = tid & 15;
            const int rg  = tid >> 4;    // rows rg*4 .. +3

            u64 acc0 = 0ull, acc1 = 0ull;
            float4 pa[4]; float pw[4];

#pragma unroll
            for (int i = 0; i < 4; i++) {
                int idx = tid + i * 256;
                int m = idx & 63, kq = (idx >> 6) * 4;
                pa[i] = *reinterpret_cast<const float4*>(&g_h[m * Hh + kq]);
                int c = idx & 15, kk = idx >> 4;
                pw[i] = Wg[(size_t)kk * (2 * Hh) + c];
            }

            for (int kt = 0; kt < Hh / 64; ++kt) {
#pragma unroll
                for (int i = 0; i < 4; i++) {
                    int idx = tid + i * 256;
                    int m = idx & 63, kq = (idx >> 6) * 4;
                    hs[kq + 0][m] = pa[i].x; hs[kq + 1][m] = pa[i].y;
                    hs[kq + 2][m] = pa[i].z; hs[kq + 3][m] = pa[i].w;
                    int c = idx & 15, kk = idx >> 4;
                    ws[kk][c] = make_float2(pw[i], pw[i]);
                }
                __syncthreads();
                if (kt + 1 < Hh / 64) {
                    int k0 = (kt + 1) * 64;
#pragma unroll
                    for (int i = 0; i < 4; i++) {
                        int idx = tid + i * 256;
                        int m = idx & 63, kq = (idx >> 6) * 4;
                        pa[i] = *reinterpret_cast<const float4*>(&g_h[m * Hh + k0 + kq]);
                        int c = idx & 15, kk = idx >> 4;
                        pw[i] = Wg[(size_t)(k0 + kk) * (2 * Hh) + c];
                    }
                }
#pragma unroll
                for (int k = 0; k < 64; k++) {
                    longlong2 a = *reinterpret_cast<const longlong2*>(&hs[k][rg * 4]);
                    u64 w2 = *reinterpret_cast<const u64*>(&ws[k][col]);
                    fma2(acc0, (u64)a.x, w2);
                    fma2(acc1, (u64)a.y, w2);
                }
                __syncthreads();
            }

            const int n = n0 + col;
            float2 v0 = unpack2(acc0), v1 = unpack2(acc1);
            float pre[4] = {v0.x, v0.y, v1.x, v1.y};
            const size_t gxb = (size_t)t * Bb * (2 * Hh);
#pragma unroll
            for (int j = 0; j < 4; j++) {
                int b = rg * 4 + j;
                float p = pre[j] + g_Gx[gxb + (size_t)b * (2 * Hh) + n];
                float s = 1.0f / (1.0f + __expf(-p));
                if (n < Hh) g_rh[b * Hh + n] = s * g_h[b * Hh + n];
                else        g_u [b * Hh + (n - Hh)] = s;
            }
        }

        GRID_BAR();

        // ---------------- Phase B: candidate + state update ----------------
        {
            const int n0  = blockIdx.x * 8;
            const int col = tid & 7;
            const int rg  = tid >> 3;    // rows rg*2, rg*2+1

            u64 acc = 0ull;
            float4 pa[4]; float pw[2];

#pragma unroll
            for (int i = 0; i < 4; i++) {
                int idx = tid + i * 256;
                int m = idx & 63, kq = (idx >> 6) * 4;
                pa[i] = *reinterpret_cast<const float4*>(&g_rh[m * Hh + kq]);
            }
#pragma unroll
            for (int i = 0; i < 2; i++) {
                int idx = tid + i * 256;
                int c = idx & 7, kk = idx >> 3;
                pw[i] = Ug[(size_t)kk * Hh + c];
            }

            for (int kt = 0; kt < Hh / 64; ++kt) {
#pragma unroll
                for (int i = 0; i < 4; i++) {
                    int idx = tid + i * 256;
                    int m = idx & 63, kq = (idx >> 6) * 4;
                    hs[kq + 0][m] = pa[i].x; hs[kq + 1][m] = pa[i].y;
                    hs[kq + 2][m] = pa[i].z; hs[kq + 3][m] = pa[i].w;
                }
#pragma unroll
                for (int i = 0; i < 2; i++) {
                    int idx = tid + i * 256;
                    int c = idx & 7, kk = idx >> 3;
                    ws[kk][c] = make_float2(pw[i], pw[i]);
                }
                __syncthreads();
                if (kt + 1 < Hh / 64) {
                    int k0 = (kt + 1) * 64;
#pragma unroll
                    for (int i = 0; i < 4; i++) {
                        int idx = tid + i * 256;
                        int m = idx & 63, kq = (idx >> 6) * 4;
                        pa[i] = *reinterpret_cast<const float4*>(&g_rh[m * Hh + k0 + kq]);
                    }
#pragma unroll
                    for (int i = 0; i < 2; i++) {
                        int idx = tid + i * 256;
                        int c = idx & 7, kk = idx >> 3;
                        pw[i] = Ug[(size_t)(k0 + kk) * Hh + c];
                    }
                }
#pragma unroll
                for (int k = 0; k < 64; k++) {
                    u64 a  = *reinterpret_cast<const u64*>(&hs[k][rg * 2]);
                    u64 w2 = *reinterpret_cast<const u64*>(&ws[k][col]);
                    fma2(acc, a, w2);
                }
                __syncthreads();
            }

            const int n = n0 + col;
            float2 v = unpack2(acc);
            const size_t cxb = (size_t)t * Bb * Hh;
#pragma unroll
            for (int j = 0; j < 2; j++) {
                int b = rg * 2 + j;
                float p  = (j ? v.y : v.x) + g_Cx[cxb + (size_t)b * Hh + n];
                float cc = tanhf(p);
                float uu = g_u[b * Hh + n];
                float ho = g_h[b * Hh + n];
                float hn = uu * ho + (1.0f - uu) * cc;
                g_h[b * Hh + n] = hn;
                out[((size_t)b * Tt + t) * Hh + n] = hn;
            }
        }

        GRID_BAR();
    }
#undef GRID_BAR
}

extern "C" void kernel_launch(void* const* d_in, const int* in_sizes, int n_in,
                              void* d_out, int out_size)
{
    const float* x  = (const float*)d_in[0];
    const float* h0 = (const float*)d_in[1];
    const float* W  = (const float*)d_in[2];
    const float* Wb = (const float*)d_in[3];
    const float* U  = (const float*)d_in[4];
    const float* Ub = (const float*)d_in[5];
    float* out = (float*)d_out;

    copy_h0<<<(Bb * Hh) / 256, 256>>>(h0);

    // Parallel x-path: Gx = x@W[:D] + W_b ; Cx = x@U[:D] + U_b
    gemm_pre<<<dim3((2 * Hh) / 64, Tt), 256>>>(x, W, Wb, 2 * Hh, 0);
    gemm_pre<<<dim3(Hh / 64, Tt), 256>>>(x, U, Ub, Hh, 1);

    // Sequential recurrence: one persistent kernel, 4 graph nodes total.
    gru_persist<<<Gblk, 256>>>(W, U, out);
}

// round 5
// speedup vs baseline: 1.0134x; 1.0134x over previous
#include <cuda_runtime.h>

typedef unsigned long long u64;

#define Bb 64
#define Tt 512
#define Dd 1024
#define Hh 1024
#define Gblk 128   // persistent grid size (<= 148 SMs, 1 CTA/SM => co-resident)

// Scratch (allocation-free rule: __device__ globals)
__device__ float g_Gx[(size_t)Tt * Bb * 2 * Hh];  // [t][b][2H] = x@W[:D] + W_b
__device__ float g_Cx[(size_t)Tt * Bb * Hh];      // [t][b][H]  = x@U[:D] + U_b
__device__ float g_h [Bb * Hh];                   // current hidden state [b][H]
__device__ float g_rh[Bb * Hh];                   // r * h
__device__ float g_u [Bb * Hh];                   // update gate
__device__ unsigned g_arrive;                      // monotonic barrier counter

// ---- packed f32x2 helpers (sm_103a: doubles FFMA throughput vs scalar) ----
__device__ __forceinline__ u64 dup2(float x) {
    u64 r; asm("mov.b64 %0, {%1, %1};" : "=l"(r) : "f"(x)); return r;
}
__device__ __forceinline__ void fma2(u64 &d, u64 a, u64 b) {
    asm("fma.rn.f32x2 %0, %1, %2, %0;" : "+l"(d) : "l"(a), "l"(b));
}
__device__ __forceinline__ float2 unpack2(u64 v) {
    float2 f; asm("mov.b64 {%0, %1}, %2;" : "=f"(f.x), "=f"(f.y) : "l"(v)); return f;
}
__device__ __forceinline__ unsigned ld_acq(const unsigned* p) {
    unsigned v; asm volatile("ld.global.acquire.gpu.u32 %0, [%1];" : "=r"(v) : "l"(p)); return v;
}

// ============================================================================
// Precompute GEMM: out[(t*64+b), n] = sum_k x[b,t,k] * Wm[k,n] + bias[n]
// Block tile 64(rows=batch) x 64(cols), BK=32, 256 threads, 4x4 per thread.
// ============================================================================
__global__ void __launch_bounds__(256) gemm_pre(
    const float* __restrict__ X,    // x as [B*T, D], row = b*T + t
    const float* __restrict__ Wm,   // [D+H, N] row-major (only rows 0..D-1 used)
    const float* __restrict__ bias, // [N]
    int N, int which)               // which: 0 -> g_Gx, 1 -> g_Cx
{
    float* __restrict__ out = which ? g_Cx : g_Gx;
    const int t   = blockIdx.y;
    const int n0  = blockIdx.x * 64;
    const int tid = threadIdx.x;
    const int tn  = tid & 15;   // col group (cols tn*4 .. +3)
    const int tm  = tid >> 4;   // row group (rows tm*4 .. +3)

    __shared__ float As[32][64];  // [k][b]
    __shared__ float Bs[32][64];  // [k][n]

    u64 acc[2][4];
#pragma unroll
    for (int i = 0; i < 2; i++)
#pragma unroll
        for (int j = 0; j < 4; j++) acc[i][j] = 0ull;

    float4 pa[2], pb[2];

#pragma unroll
    for (int i = 0; i < 2; i++) {
        int idx = tid + i * 256;
        int m = idx & 63, kq = (idx >> 6) * 4;
        pa[i] = *reinterpret_cast<const float4*>(&X[(size_t)(m * Tt + t) * Dd + kq]);
        int n4 = (idx & 15) * 4, kk = idx >> 4;
        pb[i] = *reinterpret_cast<const float4*>(&Wm[(size_t)kk * N + n0 + n4]);
    }

    for (int kt = 0; kt < Dd / 32; ++kt) {
#pragma unroll
        for (int i = 0; i < 2; i++) {
            int idx = tid + i * 256;
            int m = idx & 63, kq = (idx >> 6) * 4;
            As[kq + 0][m] = pa[i].x; As[kq + 1][m] = pa[i].y;
            As[kq + 2][m] = pa[i].z; As[kq + 3][m] = pa[i].w;
            int n4 = (idx & 15) * 4, kk = idx >> 4;
            *reinterpret_cast<float4*>(&Bs[kk][n4]) = pb[i];
        }
        __syncthreads();
        if (kt + 1 < Dd / 32) {
            int k0 = (kt + 1) * 32;
#pragma unroll
            for (int i = 0; i < 2; i++) {
                int idx = tid + i * 256;
                int m = idx & 63, kq = (idx >> 6) * 4;
                pa[i] = *reinterpret_cast<const float4*>(&X[(size_t)(m * Tt + t) * Dd + k0 + kq]);
                int n4 = (idx & 15) * 4, kk = idx >> 4;
                pb[i] = *reinterpret_cast<const float4*>(&Wm[(size_t)(k0 + kk) * N + n0 + n4]);
            }
        }
#pragma unroll
        for (int k = 0; k < 32; k++) {
            longlong2 a = *reinterpret_cast<const longlong2*>(&As[k][tm * 4]);
            float4 b4 = *reinterpret_cast<const float4*>(&Bs[k][tn * 4]);
            u64 b0 = dup2(b4.x), b1 = dup2(b4.y), b2 = dup2(b4.z), b3 = dup2(b4.w);
            fma2(acc[0][0], (u64)a.x, b0); fma2(acc[1][0], (u64)a.y, b0);
            fma2(acc[0][1], (u64)a.x, b1); fma2(acc[1][1], (u64)a.y, b1);
            fma2(acc[0][2], (u64)a.x, b2); fma2(acc[1][2], (u64)a.y, b2);
            fma2(acc[0][3], (u64)a.x, b3); fma2(acc[1][3], (u64)a.y, b3);
        }
        __syncthreads();
    }

#pragma unroll
    for (int j = 0; j < 4; j++) {
        int n = n0 + tn * 4 + j;
        float bv = bias[n];
#pragma unroll
        for (int i = 0; i < 2; i++) {
            float2 v = unpack2(acc[i][j]);
            int b0r = tm * 4 + i * 2;
            out[(size_t)(t * Bb + b0r    ) * N + n] = v.x + bv;
            out[(size_t)(t * Bb + b0r + 1) * N + n] = v.y + bv;
        }
    }
}

__global__ void copy_h0(const float* __restrict__ h0)
{
    int i = blockIdx.x * blockDim.x + threadIdx.x;
    if (i < Bb * Hh) g_h[i] = h0[i];
}

// ============================================================================
// Persistent recurrence kernel: 512 steps, 2 grid barriers per step.
// Phase A (gate): per block 16 cols of 2048:
//   pre = h @ W[D:,:] + Gx[t]; sigmoid; n<H -> rh=r*h, n>=H -> u
// Phase B (cand): per block 8 cols of 1024:
//   c = tanh(rh @ U[D:,:] + Cx[t]); h = u*h + (1-u)*c; out[b][t][n] = h
// Grid barrier: monotonic arrive counter, targets relative to entry base
// (no reset -> no reset race; replay-safe; unsigned-wrap-safe).
// ============================================================================
__global__ void __launch_bounds__(256) gru_persist(
    const float* __restrict__ W, const float* __restrict__ U,
    float* __restrict__ out)
{
    const int tid = threadIdx.x;
    __shared__ float  hs[64][64];
    __shared__ float2 ws[64][16];
    __shared__ unsigned s_base;

    if (tid == 0) s_base = ld_acq(&g_arrive);
    __syncthreads();
    const unsigned base = s_base;
    unsigned epoch = 0;

#define GRID_BAR()                                                         \
    do {                                                                   \
        __syncthreads();                                                   \
        epoch++;                                                           \
        if (tid == 0) {                                                    \
            __threadfence();                                               \
            atomicAdd(&g_arrive, 1u);                                      \
            while ((unsigned)(ld_acq(&g_arrive) - base) < epoch * Gblk) ;  \
        }                                                                  \
        __syncthreads();                                                   \
    } while (0)

    const float* __restrict__ Wg = W + (size_t)Dd * (2 * Hh) + blockIdx.x * 16;
    const float* __restrict__ Ug = U + (size_t)Dd * Hh + blockIdx.x * 8;

    for (int t = 0; t < Tt; ++t) {
        // ---------------- Phase A: gates ----------------
        {
            const int n0  = blockIdx.x * 16;
            const int col = tid & 15;
            const int rg  = tid >> 4;    // rows rg*4 .. +3

            u64 acc0 = 0ull, acc1 = 0ull;
            float4 pa[4]; float pw[4];

#pragma unroll
            for (int i = 0; i < 4; i++) {
                int idx = tid + i * 256;
                int m = idx & 63, kq = (idx >> 6) * 4;
                pa[i] = *reinterpret_cast<const float4*>(&g_h[m * Hh + kq]);
                int c = idx & 15, kk = idx >> 4;
                pw[i] = Wg[(size_t)kk * (2 * Hh) + c];
            }

            for (int kt = 0; kt < Hh / 64; ++kt) {
#pragma unroll
                for (int i = 0; i < 4; i++) {
                    int idx = tid + i * 256;
                    int m = idx & 63, kq = (idx >> 6) * 4;
                    hs[kq + 0][m] = pa[i].x; hs[kq + 1][m] = pa[i].y;
                    hs[kq + 2][m] = pa[i].z; hs[kq + 3][m] = pa[i].w;
                    int c = idx & 15, kk = idx >> 4;
                    ws[kk][c] = make_float2(pw[i], pw[i]);
                }
                __syncthreads();
                if (kt + 1 < Hh / 64) {
                    int k0 = (kt + 1) * 64;
#pragma unroll
                    for (int i = 0; i < 4; i++) {
                        int idx = tid + i * 256;
                        int m = idx & 63, kq = (idx >> 6) * 4;
                        pa[i] = *reinterpret_cast<const float4*>(&g_h[m * Hh + k0 + kq]);
                        int c = idx & 15, kk = idx >> 4;
                        pw[i] = Wg[(size_t)(k0 + kk) * (2 * Hh) + c];
                    }
                }
#pragma unroll
                for (int k = 0; k < 64; k++) {
                    longlong2 a = *reinterpret_cast<const longlong2*>(&hs[k][rg * 4]);
                    u64 w2 = *reinterpret_cast<const u64*>(&ws[k][col]);
                    fma2(acc0, (u64)a.x, w2);
                    fma2(acc1, (u64)a.y, w2);
                }
                __syncthreads();
            }

            const int n = n0 + col;
            float2 v0 = unpack2(acc0), v1 = unpack2(acc1);
            float pre[4] = {v0.x, v0.y, v1.x, v1.y};
            const size_t gxb = (size_t)t * Bb * (2 * Hh);
#pragma unroll
            for (int j = 0; j < 4; j++) {
                int b = rg * 4 + j;
                float p = pre[j] + g_Gx[gxb + (size_t)b * (2 * Hh) + n];
                float s = 1.0f / (1.0f + __expf(-p));
                if (n < Hh) g_rh[b * Hh + n] = s * g_h[b * Hh + n];
                else        g_u [b * Hh + (n - Hh)] = s;
            }
        }

        GRID_BAR();

        // ---------------- Phase B: candidate + state update ----------------
        {
            const int n0  = blockIdx.x * 8;
            const int col = tid & 7;
            const int rg  = tid >> 3;    // rows rg*2, rg*2+1

            u64 acc = 0ull;
            float4 pa[4]; float pw[2];

#pragma unroll
            for (int i = 0; i < 4; i++) {
                int idx = tid + i * 256;
                int m = idx & 63, kq = (idx >> 6) * 4;
                pa[i] = *reinterpret_cast<const float4*>(&g_rh[m * Hh + kq]);
            }
#pragma unroll
            for (int i = 0; i < 2; i++) {
                int idx = tid + i * 256;
                int c = idx & 7, kk = idx >> 3;
                pw[i] = Ug[(size_t)kk * Hh + c];
            }

            for (int kt = 0; kt < Hh / 64; ++kt) {
#pragma unroll
                for (int i = 0; i < 4; i++) {
                    int idx = tid + i * 256;
                    int m = idx & 63, kq = (idx >> 6) * 4;
                    hs[kq + 0][m] = pa[i].x; hs[kq + 1][m] = pa[i].y;
                    hs[kq + 2][m] = pa[i].z; hs[kq + 3][m] = pa[i].w;
                }
#pragma unroll
                for (int i = 0; i < 2; i++) {
                    int idx = tid + i * 256;
                    int c = idx & 7, kk = idx >> 3;
                    ws[kk][c] = make_float2(pw[i], pw[i]);
                }
                __syncthreads();
                if (kt + 1 < Hh / 64) {
                    int k0 = (kt + 1) * 64;
#pragma unroll
                    for (int i = 0; i < 4; i++) {
                        int idx = tid + i * 256;
                        int m = idx & 63, kq = (idx >> 6) * 4;
                        pa[i] = *reinterpret_cast<const float4*>(&g_rh[m * Hh + k0 + kq]);
                    }
#pragma unroll
                    for (int i = 0; i < 2; i++) {
                        int idx = tid + i * 256;
                        int c = idx & 7, kk = idx >> 3;
                        pw[i] = Ug[(size_t)(k0 + kk) * Hh + c];
                    }
                }
#pragma unroll
                for (int k = 0; k < 64; k++) {
                    u64 a  = *reinterpret_cast<const u64*>(&hs[k][rg * 2]);
                    u64 w2 = *reinterpret_cast<const u64*>(&ws[k][col]);
                    fma2(acc, a, w2);
                }
                __syncthreads();
            }

            const int n = n0 + col;
            float2 v = unpack2(acc);
            const size_t cxb = (size_t)t * Bb * Hh;
#pragma unroll
            for (int j = 0; j < 2; j++) {
                int b = rg * 2 + j;
                float p  = (j ? v.y : v.x) + g_Cx[cxb + (size_t)b * Hh + n];
                float cc = tanhf(p);
                float uu = g_u[b * Hh + n];
                float ho = g_h[b * Hh + n];
                float hn = uu * ho + (1.0f - uu) * cc;
                g_h[b * Hh + n] = hn;
                out[((size_t)b * Tt + t) * Hh + n] = hn;
            }
        }

        GRID_BAR();
    }
#undef GRID_BAR
}

extern "C" void kernel_launch(void* const* d_in, const int* in_sizes, int n_in,
                              void* d_out, int out_size)
{
    const float* x  = (const float*)d_in[0];
    const float* h0 = (const float*)d_in[1];
    const float* W  = (const float*)d_in[2];
    const float* Wb = (const float*)d_in[3];
    const float* U  = (const float*)d_in[4];
    const float* Ub = (const float*)d_in[5];
    float* out = (float*)d_out;

    copy_h0<<<(Bb * Hh) / 256, 256>>>(h0);

    // Parallel x-path: Gx = x@W[:D] + W_b ; Cx = x@U[:D] + U_b
    gemm_pre<<<dim3((2 * Hh) / 64, Tt), 256>>>(x, W, Wb, 2 * Hh, 0);
    gemm_pre<<<dim3(Hh / 64, Tt), 256>>>(x, U, Ub, Hh, 1);

    // Sequential recurrence: one persistent kernel, 4 graph nodes total.
    gru_persist<<<Gblk, 256>>>(W, U, out);
}

// round 6
// speedup vs baseline: 2.3047x; 2.2742x over previous
#include <cuda_runtime.h>

typedef unsigned long long u64;

#define Bb 64
#define Tt 512
#define Dd 1024
#define Hh 1024
#define Gblk 128   // persistent grid size (co-resident on 148 SMs)

// Scratch (allocation-free rule: __device__ globals)
__device__ float g_Gx[(size_t)Tt * Bb * 2 * Hh];  // [t][b][2H] = x@W[:D] + W_b
__device__ float g_Cx[(size_t)Tt * Bb * Hh];      // [t][b][H]  = x@U[:D] + U_b
__device__ float g_h [Bb * Hh];                   // hidden state [b][H]
__device__ float g_rh[Bb * Hh];                   // r * h
__device__ float g_u [Bb * Hh];                   // update gate
__device__ float g_pA[4 * Bb * 2 * Hh];           // gate partials [ksplit][b][2H]
__device__ float g_pB[8 * Bb * Hh];               // cand partials [ksplit][b][H]
__device__ unsigned g_arrive;                     // monotonic barrier counter

// ---- packed f32x2 helpers ----
__device__ __forceinline__ u64 dup2(float x) {
    u64 r; asm("mov.b64 %0, {%1, %1};" : "=l"(r) : "f"(x)); return r;
}
__device__ __forceinline__ void fma2(u64 &d, u64 a, u64 b) {
    asm("fma.rn.f32x2 %0, %1, %2, %0;" : "+l"(d) : "l"(a), "l"(b));
}
__device__ __forceinline__ float2 unpack2(u64 v) {
    float2 f; asm("mov.b64 {%0, %1}, %2;" : "=f"(f.x), "=f"(f.y) : "l"(v)); return f;
}
__device__ __forceinline__ unsigned ld_acq(const unsigned* p) {
    unsigned v; asm volatile("ld.global.acquire.gpu.u32 %0, [%1];" : "=r"(v) : "l"(p)); return v;
}
__device__ __forceinline__ float sigf(float x) { return 1.0f / (1.0f + __expf(-x)); }

// ============================================================================
// Precompute GEMM (x-path, unchanged): out[(t*64+b), n] = x[b,t,:] @ Wm[:D,n] + bias
// ============================================================================
__global__ void __launch_bounds__(256) gemm_pre(
    const float* __restrict__ X, const float* __restrict__ Wm,
    const float* __restrict__ bias, int N, int which)
{
    float* __restrict__ out = which ? g_Cx : g_Gx;
    const int t   = blockIdx.y;
    const int n0  = blockIdx.x * 64;
    const int tid = threadIdx.x;
    const int tn  = tid & 15;
    const int tm  = tid >> 4;

    __shared__ float As[32][64];
    __shared__ float Bs[32][64];

    u64 acc[2][4];
#pragma unroll
    for (int i = 0; i < 2; i++)
#pragma unroll
        for (int j = 0; j < 4; j++) acc[i][j] = 0ull;

    float4 pa[2], pb[2];
#pragma unroll
    for (int i = 0; i < 2; i++) {
        int idx = tid + i * 256;
        int m = idx & 63, kq = (idx >> 6) * 4;
        pa[i] = *reinterpret_cast<const float4*>(&X[(size_t)(m * Tt + t) * Dd + kq]);
        int n4 = (idx & 15) * 4, kk = idx >> 4;
        pb[i] = *reinterpret_cast<const float4*>(&Wm[(size_t)kk * N + n0 + n4]);
    }

    for (int kt = 0; kt < Dd / 32; ++kt) {
#pragma unroll
        for (int i = 0; i < 2; i++) {
            int idx = tid + i * 256;
            int m = idx & 63, kq = (idx >> 6) * 4;
            As[kq + 0][m] = pa[i].x; As[kq + 1][m] = pa[i].y;
            As[kq + 2][m] = pa[i].z; As[kq + 3][m] = pa[i].w;
            int n4 = (idx & 15) * 4, kk = idx >> 4;
            *reinterpret_cast<float4*>(&Bs[kk][n4]) = pb[i];
        }
        __syncthreads();
        if (kt + 1 < Dd / 32) {
            int k0 = (kt + 1) * 32;
#pragma unroll
            for (int i = 0; i < 2; i++) {
                int idx = tid + i * 256;
                int m = idx & 63, kq = (idx >> 6) * 4;
                pa[i] = *reinterpret_cast<const float4*>(&X[(size_t)(m * Tt + t) * Dd + k0 + kq]);
                int n4 = (idx & 15) * 4, kk = idx >> 4;
                pb[i] = *reinterpret_cast<const float4*>(&Wm[(size_t)(k0 + kk) * N + n0 + n4]);
            }
        }
#pragma unroll
        for (int k = 0; k < 32; k++) {
            longlong2 a = *reinterpret_cast<const longlong2*>(&As[k][tm * 4]);
            float4 b4 = *reinterpret_cast<const float4*>(&Bs[k][tn * 4]);
            u64 b0 = dup2(b4.x), b1 = dup2(b4.y), b2 = dup2(b4.z), b3 = dup2(b4.w);
            fma2(acc[0][0], (u64)a.x, b0); fma2(acc[1][0], (u64)a.y, b0);
            fma2(acc[0][1], (u64)a.x, b1); fma2(acc[1][1], (u64)a.y, b1);
            fma2(acc[0][2], (u64)a.x, b2); fma2(acc[1][2], (u64)a.y, b2);
            fma2(acc[0][3], (u64)a.x, b3); fma2(acc[1][3], (u64)a.y, b3);
        }
        __syncthreads();
    }

#pragma unroll
    for (int j = 0; j < 4; j++) {
        int n = n0 + tn * 4 + j;
        float bv = bias[n];
#pragma unroll
        for (int i = 0; i < 2; i++) {
            float2 v = unpack2(acc[i][j]);
            int b0r = tm * 4 + i * 2;
            out[(size_t)(t * Bb + b0r    ) * N + n] = v.x + bv;
            out[(size_t)(t * Bb + b0r + 1) * N + n] = v.y + bv;
        }
    }
}

__global__ void copy_h0(const float* __restrict__ h0)
{
    int i = blockIdx.x * blockDim.x + threadIdx.x;
    if (i < Bb * Hh) g_h[i] = h0[i];
}

// ============================================================================
// Persistent recurrence, k-split GEMM layout.
// Phase A : 128 blocks = 32 colblocks(64 cols of 2H) x 4 ksplits(256 k each).
//           64x64 tile, 4x4 f32x2 thread tiles -> partials g_pA.
// A-reduce: sum 4 partials + Gx, sigmoid -> g_rh (r*h) / g_u.
// Phase B : 128 blocks = 16 colblocks(64 cols of H) x 8 ksplits(128 k each)
//           over rh -> partials g_pB.
// B-reduce: sum 8 partials + Cx, tanh, h = u*h+(1-u)*c -> g_h, out.
// Weights live in dynamic smem, loaded ONCE for all 512 steps.
// ============================================================================
#define SM_WA (256 * 64)            // phase A weight slice [256k][64c]
#define SM_WB (128 * 64)            // phase B weight slice [128k][64c]
#define SM_HS (32 * 64)             // h staging tile [32k][64b]
#define SMEM_FLOATS (SM_WA + SM_WB + SM_HS)

__global__ void __launch_bounds__(256) gru_persist(
    const float* __restrict__ W, const float* __restrict__ U,
    float* __restrict__ out)
{
    extern __shared__ float sm[];
    float* __restrict__ wA = sm;
    float* __restrict__ wB = sm + SM_WA;
    float* __restrict__ hs = sm + SM_WA + SM_WB;

    const int tid = threadIdx.x;
    const int bx  = blockIdx.x;
    const int tn  = tid & 15;      // col group (4 cols)
    const int tm  = tid >> 4;      // row group (4 rows)
    const int ca = bx & 31, sa = bx >> 5;   // phase A decomposition
    const int cb = bx & 15, sb = bx >> 4;   // phase B decomposition

    // ---- preload weight slices into smem (once per launch) ----
    for (int i = tid; i < 256 * 16; i += 256) {
        int k = i >> 4, c4 = (i & 15) * 4;
        *reinterpret_cast<float4*>(&wA[k * 64 + c4]) =
            *reinterpret_cast<const float4*>(&W[(size_t)(Dd + sa * 256 + k) * (2 * Hh) + ca * 64 + c4]);
    }
    for (int i = tid; i < 128 * 16; i += 256) {
        int k = i >> 4, c4 = (i & 15) * 4;
        *reinterpret_cast<float4*>(&wB[k * 64 + c4]) =
            *reinterpret_cast<const float4*>(&U[(size_t)(Dd + sb * 128 + k) * Hh + cb * 64 + c4]);
    }

    __shared__ unsigned s_base;
    if (tid == 0) s_base = ld_acq(&g_arrive);
    __syncthreads();
    const unsigned base = s_base;
    unsigned epoch = 0;

#define GRID_BAR()                                                         \
    do {                                                                   \
        __syncthreads();                                                   \
        epoch++;                                                           \
        if (tid == 0) {                                                    \
            __threadfence();                                               \
            atomicAdd(&g_arrive, 1u);                                      \
            while ((unsigned)(ld_acq(&g_arrive) - base) < epoch * Gblk) ;  \
        }                                                                  \
        __syncthreads();                                                   \
    } while (0)

    for (int t = 0; t < Tt; ++t) {
        // ---------------- Phase A: gate partials ----------------
        {
            u64 acc[2][4];
#pragma unroll
            for (int i = 0; i < 2; i++)
#pragma unroll
                for (int j = 0; j < 4; j++) acc[i][j] = 0ull;

            float4 pa[2];
#pragma unroll
            for (int i = 0; i < 2; i++) {
                int idx = tid + i * 256;
                int m = idx & 63, kq = (idx >> 6) * 4;
                pa[i] = *reinterpret_cast<const float4*>(&g_h[m * Hh + sa * 256 + kq]);
            }
            for (int kt = 0; kt < 8; ++kt) {
#pragma unroll
                for (int i = 0; i < 2; i++) {
                    int idx = tid + i * 256;
                    int m = idx & 63, kq = (idx >> 6) * 4;
                    hs[(kq + 0) * 64 + m] = pa[i].x; hs[(kq + 1) * 64 + m] = pa[i].y;
                    hs[(kq + 2) * 64 + m] = pa[i].z; hs[(kq + 3) * 64 + m] = pa[i].w;
                }
                __syncthreads();
                if (kt + 1 < 8) {
                    int k0 = sa * 256 + (kt + 1) * 32;
#pragma unroll
                    for (int i = 0; i < 2; i++) {
                        int idx = tid + i * 256;
                        int m = idx & 63, kq = (idx >> 6) * 4;
                        pa[i] = *reinterpret_cast<const float4*>(&g_h[m * Hh + k0 + kq]);
                    }
                }
#pragma unroll
                for (int k = 0; k < 32; k++) {
                    longlong2 a = *reinterpret_cast<const longlong2*>(&hs[k * 64 + tm * 4]);
                    float4 w4 = *reinterpret_cast<const float4*>(&wA[(kt * 32 + k) * 64 + tn * 4]);
                    u64 b0 = dup2(w4.x), b1 = dup2(w4.y), b2 = dup2(w4.z), b3 = dup2(w4.w);
                    fma2(acc[0][0], (u64)a.x, b0); fma2(acc[1][0], (u64)a.y, b0);
                    fma2(acc[0][1], (u64)a.x, b1); fma2(acc[1][1], (u64)a.y, b1);
                    fma2(acc[0][2], (u64)a.x, b2); fma2(acc[1][2], (u64)a.y, b2);
                    fma2(acc[0][3], (u64)a.x, b3); fma2(acc[1][3], (u64)a.y, b3);
                }
                __syncthreads();
            }
            // write 4 rows x float4 of partials
            float2 v[2][4];
#pragma unroll
            for (int i = 0; i < 2; i++)
#pragma unroll
                for (int j = 0; j < 4; j++) v[i][j] = unpack2(acc[i][j]);
#pragma unroll
            for (int r = 0; r < 4; r++) {
                float4 o;
                o.x = (r & 1) ? v[r >> 1][0].y : v[r >> 1][0].x;
                o.y = (r & 1) ? v[r >> 1][1].y : v[r >> 1][1].x;
                o.z = (r & 1) ? v[r >> 1][2].y : v[r >> 1][2].x;
                o.w = (r & 1) ? v[r >> 1][3].y : v[r >> 1][3].x;
                *reinterpret_cast<float4*>(
                    &g_pA[(size_t)sa * (Bb * 2 * Hh) + (tm * 4 + r) * (2 * Hh) + ca * 64 + tn * 4]) = o;
            }
        }
        GRID_BAR();

        // ---------------- A-reduce: sigmoid gates ----------------
        {
            const int flat = bx * 1024 + tid * 4;     // = b*2048 + n
            float4 s0 = *reinterpret_cast<const float4*>(&g_pA[0 * (Bb * 2 * Hh) + flat]);
            float4 s1 = *reinterpret_cast<const float4*>(&g_pA[1 * (Bb * 2 * Hh) + flat]);
            float4 s2 = *reinterpret_cast<const float4*>(&g_pA[2 * (Bb * 2 * Hh) + flat]);
            float4 s3 = *reinterpret_cast<const float4*>(&g_pA[3 * (Bb * 2 * Hh) + flat]);
            float4 gx = *reinterpret_cast<const float4*>(&g_Gx[(size_t)t * (Bb * 2 * Hh) + flat]);
            float4 g;
            g.x = sigf(s0.x + s1.x + s2.x + s3.x + gx.x);
            g.y = sigf(s0.y + s1.y + s2.y + s3.y + gx.y);
            g.z = sigf(s0.z + s1.z + s2.z + s3.z + gx.z);
            g.w = sigf(s0.w + s1.w + s2.w + s3.w + gx.w);
            const int hidx = (bx >> 1) * 1024 + tid * 4;
            if (bx & 1) {
                *reinterpret_cast<float4*>(&g_u[hidx]) = g;
            } else {
                float4 h4 = *reinterpret_cast<const float4*>(&g_h[hidx]);
                float4 rh; rh.x = g.x * h4.x; rh.y = g.y * h4.y;
                rh.z = g.z * h4.z; rh.w = g.w * h4.w;
                *reinterpret_cast<float4*>(&g_rh[hidx]) = rh;
            }
        }
        GRID_BAR();

        // ---------------- Phase B: candidate partials ----------------
        {
            u64 acc[2][4];
#pragma unroll
            for (int i = 0; i < 2; i++)
#pragma unroll
                for (int j = 0; j < 4; j++) acc[i][j] = 0ull;

            float4 pa[2];
#pragma unroll
            for (int i = 0; i < 2; i++) {
                int idx = tid + i * 256;
                int m = idx & 63, kq = (idx >> 6) * 4;
                pa[i] = *reinterpret_cast<const float4*>(&g_rh[m * Hh + sb * 128 + kq]);
            }
            for (int kt = 0; kt < 4; ++kt) {
#pragma unroll
                for (int i = 0; i < 2; i++) {
                    int idx = tid + i * 256;
                    int m = idx & 63, kq = (idx >> 6) * 4;
                    hs[(kq + 0) * 64 + m] = pa[i].x; hs[(kq + 1) * 64 + m] = pa[i].y;
                    hs[(kq + 2) * 64 + m] = pa[i].z; hs[(kq + 3) * 64 + m] = pa[i].w;
                }
                __syncthreads();
                if (kt + 1 < 4) {
                    int k0 = sb * 128 + (kt + 1) * 32;
#pragma unroll
                    for (int i = 0; i < 2; i++) {
                        int idx = tid + i * 256;
                        int m = idx & 63, kq = (idx >> 6) * 4;
                        pa[i] = *reinterpret_cast<const float4*>(&g_rh[m * Hh + k0 + kq]);
                    }
                }
#pragma unroll
                for (int k = 0; k < 32; k++) {
                    longlong2 a = *reinterpret_cast<const longlong2*>(&hs[k * 64 + tm * 4]);
                    float4 w4 = *reinterpret_cast<const float4*>(&wB[(kt * 32 + k) * 64 + tn * 4]);
                    u64 b0 = dup2(w4.x), b1 = dup2(w4.y), b2 = dup2(w4.z), b3 = dup2(w4.w);
                    fma2(acc[0][0], (u64)a.x, b0); fma2(acc[1][0], (u64)a.y, b0);
                    fma2(acc[0][1], (u64)a.x, b1); fma2(acc[1][1], (u64)a.y, b1);
                    fma2(acc[0][2], (u64)a.x, b2); fma2(acc[1][2], (u64)a.y, b2);
                    fma2(acc[0][3], (u64)a.x, b3); fma2(acc[1][3], (u64)a.y, b3);
                }
                __syncthreads();
            }
            float2 v[2][4];
#pragma unroll
            for (int i = 0; i < 2; i++)
#pragma unroll
                for (int j = 0; j < 4; j++) v[i][j] = unpack2(acc[i][j]);
#pragma unroll
            for (int r = 0; r < 4; r++) {
                float4 o;
                o.x = (r & 1) ? v[r >> 1][0].y : v[r >> 1][0].x;
                o.y = (r & 1) ? v[r >> 1][1].y : v[r >> 1][1].x;
                o.z = (r & 1) ? v[r >> 1][2].y : v[r >> 1][2].x;
                o.w = (r & 1) ? v[r >> 1][3].y : v[r >> 1][3].x;
                *reinterpret_cast<float4*>(
                    &g_pB[(size_t)sb * (Bb * Hh) + (tm * 4 + r) * Hh + cb * 64 + tn * 4]) = o;
            }
        }
        GRID_BAR();

        // ---------------- B-reduce: tanh + state update ----------------
        if (tid < 128) {
            const int flat = bx * 512 + tid * 4;      // = b*1024 + n
            float4 acc4 = *reinterpret_cast<const float4*>(&g_Cx[(size_t)t * (Bb * Hh) + flat]);
#pragma unroll
            for (int s = 0; s < 8; s++) {
                float4 p = *reinterpret_cast<const float4*>(&g_pB[(size_t)s * (Bb * Hh) + flat]);
                acc4.x += p.x; acc4.y += p.y; acc4.z += p.z; acc4.w += p.w;
            }
            float4 u4 = *reinterpret_cast<const float4*>(&g_u[flat]);
            float4 h4 = *reinterpret_cast<const float4*>(&g_h[flat]);
            float4 hn;
            hn.x = u4.x * h4.x + (1.0f - u4.x) * tanhf(acc4.x);
            hn.y = u4.y * h4.y + (1.0f - u4.y) * tanhf(acc4.y);
            hn.z = u4.z * h4.z + (1.0f - u4.z) * tanhf(acc4.z);
            hn.w = u4.w * h4.w + (1.0f - u4.w) * tanhf(acc4.w);
            *reinterpret_cast<float4*>(&g_h[flat]) = hn;
            const int b = flat >> 10, n = flat & 1023;
            *reinterpret_cast<float4*>(&out[((size_t)b * Tt + t) * Hh + n]) = hn;
        }
        GRID_BAR();
    }
#undef GRID_BAR
}

extern "C" void kernel_launch(void* const* d_in, const int* in_sizes, int n_in,
                              void* d_out, int out_size)
{
    const float* x  = (const float*)d_in[0];
    const float* h0 = (const float*)d_in[1];
    const float* W  = (const float*)d_in[2];
    const float* Wb = (const float*)d_in[3];
    const float* U  = (const float*)d_in[4];
    const float* Ub = (const float*)d_in[5];
    float* out = (float*)d_out;

    cudaFuncSetAttribute(gru_persist, cudaFuncAttributeMaxDynamicSharedMemorySize,
                         SMEM_FLOATS * (int)sizeof(float));

    copy_h0<<<(Bb * Hh) / 256, 256>>>(h0);

    gemm_pre<<<dim3((2 * Hh) / 64, Tt), 256>>>(x, W, Wb, 2 * Hh, 0);
    gemm_pre<<<dim3(Hh / 64, Tt), 256>>>(x, U, Ub, Hh, 1);

    gru_persist<<<Gblk, 256, SMEM_FLOATS * (int)sizeof(float)>>>(W, U, out);
}